// round 1
// baseline (speedup 1.0000x reference)
#include <cuda_runtime.h>
#include <cuda_bf16.h>
#include <math.h>

// Problem constants
#define Bz   4
#define S1z  1024
#define S2z  1024
#define Dz   1024
#define Hz   16
#define DKz  64
#define FFNz 4096

// ---------------- scratch (static device allocations are the sanctioned path) ----
__device__ float g_y  [Bz * S1z * Dz];
__device__ float g_kvn[Bz * S2z * Dz];
__device__ float g_q  [Bz * S1z * Dz];
__device__ float g_k  [Bz * S2z * Dz];
__device__ float g_v  [Bz * S2z * Dz];
__device__ float g_p  [(size_t)Bz * Hz * S1z * S2z];   // attention scores, 256 MB
__device__ float g_o  [Bz * S1z * Dz];
__device__ float g_x2 [Bz * S1z * Dz];
__device__ float g_h  [Bz * S1z * FFNz];

// ---------------- LayerNorm: one block (256 thr) per row of 1024 ----------------
__global__ void ln_kernel(const float* __restrict__ in, float* __restrict__ out,
                          const float* __restrict__ g, const float* __restrict__ bta)
{
    size_t row = blockIdx.x;
    int tid = threadIdx.x;
    const float4* xp = (const float4*)(in + row * (size_t)Dz);
    float4 v = xp[tid];
    float s = v.x + v.y + v.z + v.w;
    float q = v.x*v.x + v.y*v.y + v.z*v.z + v.w*v.w;
    #pragma unroll
    for (int o = 16; o; o >>= 1) {
        s += __shfl_xor_sync(0xffffffffu, s, o);
        q += __shfl_xor_sync(0xffffffffu, q, o);
    }
    __shared__ float ss[8], qq[8];
    int lane = tid & 31, wid = tid >> 5;
    if (!lane) { ss[wid] = s; qq[wid] = q; }
    __syncthreads();
    if (tid < 32) {
        s = (tid < 8) ? ss[tid] : 0.f;
        q = (tid < 8) ? qq[tid] : 0.f;
        #pragma unroll
        for (int o = 4; o; o >>= 1) {
            s += __shfl_xor_sync(0xffffffffu, s, o);
            q += __shfl_xor_sync(0xffffffffu, q, o);
        }
        if (!tid) { ss[0] = s; qq[0] = q; }
    }
    __syncthreads();
    float mean = ss[0] * (1.f / Dz);
    float var  = qq[0] * (1.f / Dz) - mean * mean;
    float inv  = rsqrtf(var + 1e-5f);
    float4 gv = ((const float4*)g)[tid];
    float4 bv = ((const float4*)bta)[tid];
    float4 o4;
    o4.x = (v.x - mean) * inv * gv.x + bv.x;
    o4.y = (v.y - mean) * inv * gv.y + bv.y;
    o4.z = (v.z - mean) * inv * gv.z + bv.z;
    o4.w = (v.w - mean) * inv * gv.w + bv.w;
    ((float4*)(out + row * (size_t)Dz))[tid] = o4;
}

// ---------------- masked softmax over rows of S2=1024 ---------------------------
__global__ void softmax_kernel(float* __restrict__ P, const int* __restrict__ mask)
{
    size_t row = blockIdx.x;                      // [0, B*H*S1)
    int b = (int)(row / ((size_t)Hz * S1z));
    float* p = P + row * (size_t)S2z;
    const int4* m4 = (const int4*)(mask + (size_t)b * S2z);
    int tid = threadIdx.x;
    float4 v = ((const float4*)p)[tid];
    int4 mk = m4[tid];
    v.x = mk.x ? v.x * 0.125f : -1e9f;
    v.y = mk.y ? v.y * 0.125f : -1e9f;
    v.z = mk.z ? v.z * 0.125f : -1e9f;
    v.w = mk.w ? v.w * 0.125f : -1e9f;

    float mx = fmaxf(fmaxf(v.x, v.y), fmaxf(v.z, v.w));
    #pragma unroll
    for (int o = 16; o; o >>= 1) mx = fmaxf(mx, __shfl_xor_sync(0xffffffffu, mx, o));
    __shared__ float sh[8];
    int lane = tid & 31, wid = tid >> 5;
    if (!lane) sh[wid] = mx;
    __syncthreads();
    if (tid < 32) {
        float t = (tid < 8) ? sh[tid] : -3.4e38f;
        #pragma unroll
        for (int o = 4; o; o >>= 1) t = fmaxf(t, __shfl_xor_sync(0xffffffffu, t, o));
        if (!tid) sh[0] = t;
    }
    __syncthreads();
    mx = sh[0];
    v.x = __expf(v.x - mx);
    v.y = __expf(v.y - mx);
    v.z = __expf(v.z - mx);
    v.w = __expf(v.w - mx);
    float s = v.x + v.y + v.z + v.w;
    __syncthreads();                              // protect sh reuse
    #pragma unroll
    for (int o = 16; o; o >>= 1) s += __shfl_xor_sync(0xffffffffu, s, o);
    if (!lane) sh[wid] = s;
    __syncthreads();
    if (tid < 32) {
        float t = (tid < 8) ? sh[tid] : 0.f;
        #pragma unroll
        for (int o = 4; o; o >>= 1) t += __shfl_xor_sync(0xffffffffu, t, o);
        if (!tid) sh[0] = t;
    }
    __syncthreads();
    float inv = 1.0f / sh[0];
    v.x *= inv; v.y *= inv; v.z *= inv; v.w *= inv;
    ((float4*)p)[tid] = v;
}

// ---------------- elementwise add ------------------------------------------------
__global__ void add_kernel(const float* __restrict__ a, const float* __restrict__ b,
                           float* __restrict__ c)
{
    int i = blockIdx.x * blockDim.x + threadIdx.x;
    float4 av = ((const float4*)a)[i];
    float4 bv = ((const float4*)b)[i];
    float4 cv;
    cv.x = av.x + bv.x; cv.y = av.y + bv.y; cv.z = av.z + bv.z; cv.w = av.w + bv.w;
    ((float4*)c)[i] = cv;
}

// ---------------- generic tiled SGEMM (NN or NT), batched via blockIdx.z ---------
// C[M,N] = A[M,K] @ B,  B row-major [K,N] (TB=false) or [N,K] (TB=true → A·Bᵀ)
// epilogue: + bias[n] (if bias), + res[m,n] (if res), relu (if relu)
template<int BM, int BN, int BK, int TM, int TN, bool TB>
__global__ void __launch_bounds__((BM/TM)*(BN/TN))
sgemm(int M, int N, int K,
      const float* __restrict__ A, int lda,
      const float* __restrict__ Bp, int ldb,
      float* __restrict__ C, int ldc,
      const float* __restrict__ bias,
      const float* __restrict__ res, int ldres,
      int relu,
      long sAb, long sAh, long sBb, long sBh, long sCb, long sCh, int Hn)
{
    constexpr int THREADS = (BM/TM) * (BN/TN);
    __shared__ float As[BK][BM];
    __shared__ float Bs[BK][BN];

    int zz = blockIdx.z;
    int bb = zz / Hn, hh = zz % Hn;
    A  += (size_t)bb * sAb + (size_t)hh * sAh;
    Bp += (size_t)bb * sBb + (size_t)hh * sBh;
    C  += (size_t)bb * sCb + (size_t)hh * sCh;

    int tid = threadIdx.x;
    int bm = blockIdx.y * BM, bn = blockIdx.x * BN;
    int tx = tid % (BN/TN), ty = tid / (BN/TN);

    float acc[TM][TN] = {};
    float ar[TM], br[TN];

    for (int k0 = 0; k0 < K; k0 += BK) {
        // load A tile (vectorized along K, stored transposed)
        for (int vv = tid; vv < BM * (BK/4); vv += THREADS) {
            int r = vv / (BK/4);
            int c = (vv % (BK/4)) * 4;
            float4 a4 = *(const float4*)(A + (size_t)(bm + r) * lda + k0 + c);
            As[c+0][r] = a4.x; As[c+1][r] = a4.y; As[c+2][r] = a4.z; As[c+3][r] = a4.w;
        }
        if (TB) {
            // B is [N,K] row-major; vectorize along K, store transposed
            for (int vv = tid; vv < BN * (BK/4); vv += THREADS) {
                int r = vv / (BK/4);
                int c = (vv % (BK/4)) * 4;
                float4 b4 = *(const float4*)(Bp + (size_t)(bn + r) * ldb + k0 + c);
                Bs[c+0][r] = b4.x; Bs[c+1][r] = b4.y; Bs[c+2][r] = b4.z; Bs[c+3][r] = b4.w;
            }
        } else {
            // B is [K,N] row-major; vectorize along N
            for (int vv = tid; vv < BK * (BN/4); vv += THREADS) {
                int r = vv / (BN/4);
                int c = (vv % (BN/4)) * 4;
                *(float4*)&Bs[r][c] = *(const float4*)(Bp + (size_t)(k0 + r) * ldb + bn + c);
            }
        }
        __syncthreads();

        #pragma unroll
        for (int kk = 0; kk < BK; kk++) {
            #pragma unroll
            for (int i = 0; i < TM; i++) ar[i] = As[kk][ty*TM + i];
            #pragma unroll
            for (int j = 0; j < TN; j++) br[j] = Bs[kk][tx*TN + j];
            #pragma unroll
            for (int i = 0; i < TM; i++)
                #pragma unroll
                for (int j = 0; j < TN; j++)
                    acc[i][j] += ar[i] * br[j];
        }
        __syncthreads();
    }

    #pragma unroll
    for (int i = 0; i < TM; i++) {
        int m = bm + ty*TM + i;
        #pragma unroll
        for (int j = 0; j < TN; j++) {
            int n = bn + tx*TN + j;
            float c = acc[i][j];
            if (bias) c += bias[n];
            if (res)  c += res[(size_t)m * ldres + n];
            if (relu) c = fmaxf(c, 0.f);
            C[(size_t)m * ldc + n] = c;
        }
    }
}

// ---------------- host orchestration --------------------------------------------
extern "C" void kernel_launch(void* const* d_in, const int* in_sizes, int n_in,
                              void* d_out, int out_size)
{
    const float* x     = (const float*)d_in[0];
    const float* kv    = (const float*)d_in[1];
    const int*   mask  = (const int*)  d_in[2];
    const float* ln1_g = (const float*)d_in[3];
    const float* ln1_b = (const float*)d_in[4];
    const float* qw[2] = { (const float*)d_in[5],  (const float*)d_in[10] };
    const float* kw[2] = { (const float*)d_in[6],  (const float*)d_in[11] };
    const float* vw[2] = { (const float*)d_in[7],  (const float*)d_in[12] };
    const float* ow[2] = { (const float*)d_in[8],  (const float*)d_in[13] };
    const float* ob[2] = { (const float*)d_in[9],  (const float*)d_in[14] };
    const float* ln2_g = (const float*)d_in[15];
    const float* ln2_b = (const float*)d_in[16];
    const float* w1    = (const float*)d_in[17];
    const float* b1    = (const float*)d_in[18];
    const float* w2    = (const float*)d_in[19];
    const float* b2    = (const float*)d_in[20];
    float* out = (float*)d_out;

    float *y, *kvn, *q, *k, *v, *p, *o, *x2, *hbuf;
    cudaGetSymbolAddress((void**)&y,    g_y);
    cudaGetSymbolAddress((void**)&kvn,  g_kvn);
    cudaGetSymbolAddress((void**)&q,    g_q);
    cudaGetSymbolAddress((void**)&k,    g_k);
    cudaGetSymbolAddress((void**)&v,    g_v);
    cudaGetSymbolAddress((void**)&p,    g_p);
    cudaGetSymbolAddress((void**)&o,    g_o);
    cudaGetSymbolAddress((void**)&x2,   g_x2);
    cudaGetSymbolAddress((void**)&hbuf, g_h);

    const int M = Bz * S1z;   // 4096

    // LN of x and kv (shared ln1 params)
    ln_kernel<<<Bz * S1z, 256>>>(x,  y,   ln1_g, ln1_b);
    ln_kernel<<<Bz * S2z, 256>>>(kv, kvn, ln1_g, ln1_b);

    dim3 gProj(Dz/128, M/128);            // (8, 32)
    dim3 gScore(S2z/128, S1z/128, Bz*Hz); // (8, 8, 64)
    dim3 gPV(DKz/64, S1z/128, Bz*Hz);     // (1, 8, 64)

    for (int l = 0; l < 2; l++) {
        // Q/K/V projections
        sgemm<128,128,8,8,8,false><<<gProj, 256>>>(M, Dz, Dz, y,   Dz, qw[l], Dz, q, Dz,
            nullptr, nullptr, 0, 0, 0,0,0,0,0,0, 1);
        sgemm<128,128,8,8,8,false><<<gProj, 256>>>(M, Dz, Dz, kvn, Dz, kw[l], Dz, k, Dz,
            nullptr, nullptr, 0, 0, 0,0,0,0,0,0, 1);
        sgemm<128,128,8,8,8,false><<<gProj, 256>>>(M, Dz, Dz, kvn, Dz, vw[l], Dz, v, Dz,
            nullptr, nullptr, 0, 0, 0,0,0,0,0,0, 1);

        // scores S[b,h] = Q_bh @ K_bhᵀ   (scale applied in softmax)
        sgemm<128,128,8,8,8,true><<<gScore, 256>>>(S1z, S2z, DKz, q, Dz, k, Dz, p, S2z,
            nullptr, nullptr, 0, 0,
            (long)S1z*Dz, DKz, (long)S2z*Dz, DKz,
            (long)Hz*S1z*S2z, (long)S1z*S2z, Hz);

        // masked softmax (scale 1/8 + mask fused)
        softmax_kernel<<<Bz*Hz*S1z, 256>>>(p, mask);

        // O[b,h] = P @ V_bh
        sgemm<128,64,16,8,4,false><<<gPV, 256>>>(S1z, DKz, S2z, p, S2z, v, Dz, o, Dz,
            nullptr, nullptr, 0, 0,
            (long)Hz*S1z*S2z, (long)S1z*S2z, (long)S2z*Dz, DKz,
            (long)S1z*Dz, DKz, Hz);

        // y = O @ ow + ob + y   (residual fused into epilogue)
        sgemm<128,128,8,8,8,false><<<gProj, 256>>>(M, Dz, Dz, o, Dz, ow[l], Dz, y, Dz,
            ob[l], y, Dz, 0, 0,0,0,0,0,0, 1);
    }

    // x2 = x + y
    add_kernel<<<(M * Dz) / (256 * 4), 256>>>(x, y, x2);

    // y = LN(x2)
    ln_kernel<<<M, 256>>>(x2, y, ln2_g, ln2_b);

    // h = relu(y @ w1 + b1)
    dim3 gF1(FFNz/128, M/128);            // (32, 32)
    sgemm<128,128,8,8,8,false><<<gF1, 256>>>(M, FFNz, Dz, y, Dz, w1, FFNz, hbuf, FFNz,
        b1, nullptr, 0, 1, 0,0,0,0,0,0, 1);

    // out = h @ w2 + b2 + x2
    sgemm<128,128,8,8,8,false><<<gProj, 256>>>(M, Dz, FFNz, hbuf, FFNz, w2, Dz, out, Dz,
        b2, x2, Dz, 0, 0,0,0,0,0,0, 1);
}

// round 2
// speedup vs baseline: 3.1855x; 3.1855x over previous
#include <cuda_runtime.h>
#include <cuda_bf16.h>
#include <cstdint>
#include <math.h>

// Problem constants
#define Bz   4
#define S1z  1024
#define S2z  1024
#define Dz   1024
#define Hz   16
#define DKz  64
#define FFNz 4096

// ---------------- scratch ----------------
__device__ float g_y  [Bz * S1z * Dz];
__device__ float g_kvn[Bz * S2z * Dz];
__device__ float g_q  [Bz * S1z * Dz];
__device__ float g_k  [Bz * S2z * Dz];
__device__ float g_v  [Bz * S2z * Dz];
__device__ float g_p  [(size_t)Bz * Hz * S1z * S2z];
__device__ float g_o  [Bz * S1z * Dz];
__device__ float g_x2 [Bz * S1z * Dz];
__device__ float g_h  [Bz * S1z * FFNz];

// ---------------- LayerNorm ----------------
__global__ void ln_kernel(const float* __restrict__ in, float* __restrict__ out,
                          const float* __restrict__ g, const float* __restrict__ bta)
{
    size_t row = blockIdx.x;
    int tid = threadIdx.x;
    const float4* xp = (const float4*)(in + row * (size_t)Dz);
    float4 v = xp[tid];
    float s = v.x + v.y + v.z + v.w;
    float q = v.x*v.x + v.y*v.y + v.z*v.z + v.w*v.w;
    #pragma unroll
    for (int o = 16; o; o >>= 1) {
        s += __shfl_xor_sync(0xffffffffu, s, o);
        q += __shfl_xor_sync(0xffffffffu, q, o);
    }
    __shared__ float ss[8], qq[8];
    int lane = tid & 31, wid = tid >> 5;
    if (!lane) { ss[wid] = s; qq[wid] = q; }
    __syncthreads();
    if (tid < 32) {
        s = (tid < 8) ? ss[tid] : 0.f;
        q = (tid < 8) ? qq[tid] : 0.f;
        #pragma unroll
        for (int o = 4; o; o >>= 1) {
            s += __shfl_xor_sync(0xffffffffu, s, o);
            q += __shfl_xor_sync(0xffffffffu, q, o);
        }
        if (!tid) { ss[0] = s; qq[0] = q; }
    }
    __syncthreads();
    float mean = ss[0] * (1.f / Dz);
    float var  = qq[0] * (1.f / Dz) - mean * mean;
    float inv  = rsqrtf(var + 1e-5f);
    float4 gv = ((const float4*)g)[tid];
    float4 bv = ((const float4*)bta)[tid];
    float4 o4;
    o4.x = (v.x - mean) * inv * gv.x + bv.x;
    o4.y = (v.y - mean) * inv * gv.y + bv.y;
    o4.z = (v.z - mean) * inv * gv.z + bv.z;
    o4.w = (v.w - mean) * inv * gv.w + bv.w;
    ((float4*)(out + row * (size_t)Dz))[tid] = o4;
}

// ---------------- masked softmax ----------------
__global__ void softmax_kernel(float* __restrict__ P, const int* __restrict__ mask)
{
    size_t row = blockIdx.x;
    int b = (int)(row / ((size_t)Hz * S1z));
    float* p = P + row * (size_t)S2z;
    const int4* m4 = (const int4*)(mask + (size_t)b * S2z);
    int tid = threadIdx.x;
    float4 v = ((const float4*)p)[tid];
    int4 mk = m4[tid];
    v.x = mk.x ? v.x * 0.125f : -1e9f;
    v.y = mk.y ? v.y * 0.125f : -1e9f;
    v.z = mk.z ? v.z * 0.125f : -1e9f;
    v.w = mk.w ? v.w * 0.125f : -1e9f;

    float mx = fmaxf(fmaxf(v.x, v.y), fmaxf(v.z, v.w));
    #pragma unroll
    for (int o = 16; o; o >>= 1) mx = fmaxf(mx, __shfl_xor_sync(0xffffffffu, mx, o));
    __shared__ float sh[8];
    int lane = tid & 31, wid = tid >> 5;
    if (!lane) sh[wid] = mx;
    __syncthreads();
    if (tid < 32) {
        float t = (tid < 8) ? sh[tid] : -3.4e38f;
        #pragma unroll
        for (int o = 4; o; o >>= 1) t = fmaxf(t, __shfl_xor_sync(0xffffffffu, t, o));
        if (!tid) sh[0] = t;
    }
    __syncthreads();
    mx = sh[0];
    v.x = __expf(v.x - mx);
    v.y = __expf(v.y - mx);
    v.z = __expf(v.z - mx);
    v.w = __expf(v.w - mx);
    float s = v.x + v.y + v.z + v.w;
    __syncthreads();
    #pragma unroll
    for (int o = 16; o; o >>= 1) s += __shfl_xor_sync(0xffffffffu, s, o);
    if (!lane) sh[wid] = s;
    __syncthreads();
    if (tid < 32) {
        float t = (tid < 8) ? sh[tid] : 0.f;
        #pragma unroll
        for (int o = 4; o; o >>= 1) t += __shfl_xor_sync(0xffffffffu, t, o);
        if (!tid) sh[0] = t;
    }
    __syncthreads();
    float inv = 1.0f / sh[0];
    v.x *= inv; v.y *= inv; v.z *= inv; v.w *= inv;
    ((float4*)p)[tid] = v;
}

// ---------------- elementwise add ----------------
__global__ void add_kernel(const float* __restrict__ a, const float* __restrict__ b,
                           float* __restrict__ c)
{
    int i = blockIdx.x * blockDim.x + threadIdx.x;
    float4 av = ((const float4*)a)[i];
    float4 bv = ((const float4*)b)[i];
    float4 cv;
    cv.x = av.x + bv.x; cv.y = av.y + bv.y; cv.z = av.z + bv.z; cv.w = av.w + bv.w;
    ((float4*)c)[i] = cv;
}

// ---------------- tf32 tensor-core GEMM -------------------------------------
__device__ __forceinline__ uint32_t f2tf(float x) {
    uint32_t u; asm("cvt.rna.tf32.f32 %0, %1;" : "=r"(u) : "f"(x)); return u;
}

__device__ __forceinline__ void mma_tf32(float* c, const uint32_t* a, const uint32_t* b) {
    asm volatile("mma.sync.aligned.m16n8k8.row.col.f32.tf32.tf32.f32 "
                 "{%0,%1,%2,%3},{%4,%5,%6,%7},{%8,%9},{%0,%1,%2,%3};"
                 : "+f"(c[0]), "+f"(c[1]), "+f"(c[2]), "+f"(c[3])
                 : "r"(a[0]), "r"(a[1]), "r"(a[2]), "r"(a[3]), "r"(b[0]), "r"(b[1]));
}

// C[M,N] = A[M,K] @ B.  TB=false: B row-major [K,N]; TB=true: B row-major [N,K] (A·Bᵀ).
// Batched over blockIdx.z via per-batch/head strides. All dims exact multiples of tiles.
template<int BM, int BN, int WM, int WN, bool TB>
__global__ void __launch_bounds__((BM/WM)*(BN/WN)*32)
tgemm(int K,
      const float* __restrict__ A, int lda,
      const float* __restrict__ B, int ldb,
      float* __restrict__ C, int ldc,
      const float* __restrict__ bias,
      const float* __restrict__ res, int ldres, int relu,
      long sAb, long sAh, long sBb, long sBh, long sCb, long sCh, int Hn)
{
    constexpr int BK = 16;
    constexpr int NWARP = (BM/WM)*(BN/WN);
    constexpr int THREADS = NWARP*32;
    constexpr int ASTR = BK + 4;                    // 20: conflict-free A frag LDS
    constexpr int BSTR = TB ? (BK + 4) : (BN + 8);  // NT: 20; NN: (BN+8)%32==8
    constexpr int BROWS = TB ? BN : BK;
    constexpr int MI = WM/16, NJ = WN/8;

    __shared__ __align__(16) float As[2][BM*ASTR];
    __shared__ __align__(16) float Bs[2][BROWS*BSTR];

    int zz = blockIdx.z, bb = zz / Hn, hh = zz % Hn;
    A += (size_t)bb*sAb + (size_t)hh*sAh;
    B += (size_t)bb*sBb + (size_t)hh*sBh;
    C += (size_t)bb*sCb + (size_t)hh*sCh;

    int tid = threadIdx.x;
    int bm = blockIdx.y*BM, bn = blockIdx.x*BN;
    int warp = tid >> 5, lane = tid & 31, g = lane >> 2, tg = lane & 3;
    constexpr int WNC = BN/WN;
    int wn = warp % WNC, wm = warp / WNC;

    uint32_t asb = (uint32_t)__cvta_generic_to_shared(&As[0][0]);
    uint32_t bsb = (uint32_t)__cvta_generic_to_shared(&Bs[0][0]);

    const int NT = K / BK;

    auto issue = [&](int kt) {
        int buf = kt & 1;
        #pragma unroll
        for (int e = tid; e < BM*(BK/4); e += THREADS) {
            int r = e >> 2, c = (e & 3) * 4;
            uint32_t d = asb + (uint32_t)(buf*BM*ASTR + r*ASTR + c) * 4u;
            const float* s = A + (size_t)(bm + r) * lda + kt*BK + c;
            asm volatile("cp.async.cg.shared.global [%0], [%1], 16;" :: "r"(d), "l"(s));
        }
        if (TB) {
            #pragma unroll
            for (int e = tid; e < BN*(BK/4); e += THREADS) {
                int r = e >> 2, c = (e & 3) * 4;
                uint32_t d = bsb + (uint32_t)(buf*BROWS*BSTR + r*BSTR + c) * 4u;
                const float* s = B + (size_t)(bn + r) * ldb + kt*BK + c;
                asm volatile("cp.async.cg.shared.global [%0], [%1], 16;" :: "r"(d), "l"(s));
            }
        } else {
            #pragma unroll
            for (int e = tid; e < BK*(BN/4); e += THREADS) {
                int r = e / (BN/4), c = (e % (BN/4)) * 4;
                uint32_t d = bsb + (uint32_t)(buf*BROWS*BSTR + r*BSTR + c) * 4u;
                const float* s = B + (size_t)(kt*BK + r) * ldb + bn + c;
                asm volatile("cp.async.cg.shared.global [%0], [%1], 16;" :: "r"(d), "l"(s));
            }
        }
        asm volatile("cp.async.commit_group;");
    };

    float acc[MI][NJ][4] = {};

    issue(0);
    for (int kt = 0; kt < NT; kt++) {
        if (kt + 1 < NT) {
            issue(kt + 1);
            asm volatile("cp.async.wait_group 1;");
        } else {
            asm volatile("cp.async.wait_group 0;");
        }
        __syncthreads();

        int buf = kt & 1;
        const float* ap = &As[buf][0];
        const float* bp = &Bs[buf][0];
        #pragma unroll
        for (int ks = 0; ks < 2; ks++) {
            uint32_t a[MI][4], b[NJ][2];
            #pragma unroll
            for (int mi = 0; mi < MI; mi++) {
                int m0 = wm*WM + mi*16 + g;
                a[mi][0] = f2tf(ap[(m0    )*ASTR + ks*8 + tg    ]);
                a[mi][1] = f2tf(ap[(m0 + 8)*ASTR + ks*8 + tg    ]);
                a[mi][2] = f2tf(ap[(m0    )*ASTR + ks*8 + tg + 4]);
                a[mi][3] = f2tf(ap[(m0 + 8)*ASTR + ks*8 + tg + 4]);
            }
            #pragma unroll
            for (int j = 0; j < NJ; j++) {
                int n0 = wn*WN + j*8 + g;
                if (TB) {
                    b[j][0] = f2tf(bp[n0*BSTR + ks*8 + tg    ]);
                    b[j][1] = f2tf(bp[n0*BSTR + ks*8 + tg + 4]);
                } else {
                    b[j][0] = f2tf(bp[(ks*8 + tg    )*BSTR + n0]);
                    b[j][1] = f2tf(bp[(ks*8 + tg + 4)*BSTR + n0]);
                }
            }
            #pragma unroll
            for (int mi = 0; mi < MI; mi++)
                #pragma unroll
                for (int j = 0; j < NJ; j++)
                    mma_tf32(acc[mi][j], a[mi], b[j]);
        }
        __syncthreads();
    }

    // epilogue
    #pragma unroll
    for (int mi = 0; mi < MI; mi++) {
        #pragma unroll
        for (int j = 0; j < NJ; j++) {
            int m0 = bm + wm*WM + mi*16 + g;
            int n0 = bn + wn*WN + j*8 + 2*tg;
            float v0 = acc[mi][j][0], v1 = acc[mi][j][1];
            float v2 = acc[mi][j][2], v3 = acc[mi][j][3];
            if (bias) {
                float b0 = bias[n0], b1 = bias[n0 + 1];
                v0 += b0; v1 += b1; v2 += b0; v3 += b1;
            }
            if (res) {
                v0 += res[(size_t)m0*ldres + n0];
                v1 += res[(size_t)m0*ldres + n0 + 1];
                v2 += res[(size_t)(m0 + 8)*ldres + n0];
                v3 += res[(size_t)(m0 + 8)*ldres + n0 + 1];
            }
            if (relu) {
                v0 = fmaxf(v0, 0.f); v1 = fmaxf(v1, 0.f);
                v2 = fmaxf(v2, 0.f); v3 = fmaxf(v3, 0.f);
            }
            *(float2*)&C[(size_t)m0*ldc + n0]       = make_float2(v0, v1);
            *(float2*)&C[(size_t)(m0 + 8)*ldc + n0] = make_float2(v2, v3);
        }
    }
}

// ---------------- host orchestration ----------------
extern "C" void kernel_launch(void* const* d_in, const int* in_sizes, int n_in,
                              void* d_out, int out_size)
{
    const float* x     = (const float*)d_in[0];
    const float* kv    = (const float*)d_in[1];
    const int*   mask  = (const int*)  d_in[2];
    const float* ln1_g = (const float*)d_in[3];
    const float* ln1_b = (const float*)d_in[4];
    const float* qw[2] = { (const float*)d_in[5],  (const float*)d_in[10] };
    const float* kw[2] = { (const float*)d_in[6],  (const float*)d_in[11] };
    const float* vw[2] = { (const float*)d_in[7],  (const float*)d_in[12] };
    const float* ow[2] = { (const float*)d_in[8],  (const float*)d_in[13] };
    const float* ob[2] = { (const float*)d_in[9],  (const float*)d_in[14] };
    const float* ln2_g = (const float*)d_in[15];
    const float* ln2_b = (const float*)d_in[16];
    const float* w1    = (const float*)d_in[17];
    const float* b1    = (const float*)d_in[18];
    const float* w2    = (const float*)d_in[19];
    const float* b2    = (const float*)d_in[20];
    float* out = (float*)d_out;

    float *y, *kvn, *q, *k, *v, *p, *o, *x2, *hbuf;
    cudaGetSymbolAddress((void**)&y,    g_y);
    cudaGetSymbolAddress((void**)&kvn,  g_kvn);
    cudaGetSymbolAddress((void**)&q,    g_q);
    cudaGetSymbolAddress((void**)&k,    g_k);
    cudaGetSymbolAddress((void**)&v,    g_v);
    cudaGetSymbolAddress((void**)&p,    g_p);
    cudaGetSymbolAddress((void**)&o,    g_o);
    cudaGetSymbolAddress((void**)&x2,   g_x2);
    cudaGetSymbolAddress((void**)&hbuf, g_h);

    const int M = Bz * S1z;   // 4096

    ln_kernel<<<Bz * S1z, 256>>>(x,  y,   ln1_g, ln1_b);
    ln_kernel<<<Bz * S2z, 256>>>(kv, kvn, ln1_g, ln1_b);

    dim3 gProj(Dz/128, M/128);            // (8, 32)
    dim3 gScore(S2z/128, S1z/128, Bz*Hz); // (8, 8, 64)
    dim3 gPV(1, S1z/128, Bz*Hz);          // (1, 8, 64)

    for (int l = 0; l < 2; l++) {
        // Q/K/V projections (tf32 MMA)
        tgemm<128,128,32,64,false><<<gProj, 256>>>(Dz, y,   Dz, qw[l], Dz, q, Dz,
            nullptr, nullptr, 0, 0, 0,0,0,0,0,0, 1);
        tgemm<128,128,32,64,false><<<gProj, 256>>>(Dz, kvn, Dz, kw[l], Dz, k, Dz,
            nullptr, nullptr, 0, 0, 0,0,0,0,0,0, 1);
        tgemm<128,128,32,64,false><<<gProj, 256>>>(Dz, kvn, Dz, vw[l], Dz, v, Dz,
            nullptr, nullptr, 0, 0, 0,0,0,0,0,0, 1);

        // scores S[b,h] = Q_bh @ K_bhᵀ
        tgemm<128,128,32,64,true><<<gScore, 256>>>(DKz, q, Dz, k, Dz, p, S2z,
            nullptr, nullptr, 0, 0,
            (long)S1z*Dz, DKz, (long)S2z*Dz, DKz,
            (long)Hz*S1z*S2z, (long)S1z*S2z, Hz);

        // masked softmax
        softmax_kernel<<<Bz*Hz*S1z, 256>>>(p, mask);

        // O[b,h] = P @ V_bh
        tgemm<128,64,16,64,false><<<gPV, 256>>>(S2z, p, S2z, v, Dz, o, Dz,
            nullptr, nullptr, 0, 0,
            (long)Hz*S1z*S2z, (long)S1z*S2z, (long)S2z*Dz, DKz,
            (long)S1z*Dz, DKz, Hz);

        // y = O @ ow + ob + y
        tgemm<128,128,32,64,false><<<gProj, 256>>>(Dz, o, Dz, ow[l], Dz, y, Dz,
            ob[l], y, Dz, 0, 0,0,0,0,0,0, 1);
    }

    // x2 = x + y
    add_kernel<<<(M * Dz) / (256 * 4), 256>>>(x, y, x2);

    // y = LN(x2)
    ln_kernel<<<M, 256>>>(x2, y, ln2_g, ln2_b);

    // h = relu(y @ w1 + b1)
    dim3 gF1(FFNz/128, M/128);            // (32, 32)
    tgemm<128,128,32,64,false><<<gF1, 256>>>(Dz, y, Dz, w1, FFNz, hbuf, FFNz,
        b1, nullptr, 0, 1, 0,0,0,0,0,0, 1);

    // out = h @ w2 + b2 + x2
    tgemm<128,128,32,64,false><<<gProj, 256>>>(FFNz, hbuf, FFNz, w2, Dz, out, Dz,
        b2, x2, Dz, 0, 0,0,0,0,0,0, 1);
}

// round 3
// speedup vs baseline: 3.8442x; 1.2068x over previous
#include <cuda_runtime.h>
#include <cuda_bf16.h>
#include <cstdint>
#include <math.h>

// Problem constants
#define Bz   4
#define S1z  1024
#define S2z  1024
#define Dz   1024
#define Hz   16
#define DKz  64
#define FFNz 4096

// ---------------- scratch ----------------
__device__ float g_y  [Bz * S1z * Dz];
__device__ float g_kvn[Bz * S2z * Dz];
__device__ float g_q  [Bz * S1z * Dz];
__device__ float g_k  [Bz * S2z * Dz];
__device__ float g_v  [Bz * S2z * Dz];
__device__ float g_o  [Bz * S1z * Dz];
__device__ float g_x2 [Bz * S1z * Dz];
__device__ float g_h  [Bz * S1z * FFNz];

// ---------------- LayerNorm ----------------
__global__ void ln_kernel(const float* __restrict__ in, float* __restrict__ out,
                          const float* __restrict__ g, const float* __restrict__ bta)
{
    size_t row = blockIdx.x;
    int tid = threadIdx.x;
    const float4* xp = (const float4*)(in + row * (size_t)Dz);
    float4 v = xp[tid];
    float s = v.x + v.y + v.z + v.w;
    float q = v.x*v.x + v.y*v.y + v.z*v.z + v.w*v.w;
    #pragma unroll
    for (int o = 16; o; o >>= 1) {
        s += __shfl_xor_sync(0xffffffffu, s, o);
        q += __shfl_xor_sync(0xffffffffu, q, o);
    }
    __shared__ float ss[8], qq[8];
    int lane = tid & 31, wid = tid >> 5;
    if (!lane) { ss[wid] = s; qq[wid] = q; }
    __syncthreads();
    if (tid < 32) {
        s = (tid < 8) ? ss[tid] : 0.f;
        q = (tid < 8) ? qq[tid] : 0.f;
        #pragma unroll
        for (int o = 4; o; o >>= 1) {
            s += __shfl_xor_sync(0xffffffffu, s, o);
            q += __shfl_xor_sync(0xffffffffu, q, o);
        }
        if (!tid) { ss[0] = s; qq[0] = q; }
    }
    __syncthreads();
    float mean = ss[0] * (1.f / Dz);
    float var  = qq[0] * (1.f / Dz) - mean * mean;
    float inv  = rsqrtf(var + 1e-5f);
    float4 gv = ((const float4*)g)[tid];
    float4 bv = ((const float4*)bta)[tid];
    float4 o4;
    o4.x = (v.x - mean) * inv * gv.x + bv.x;
    o4.y = (v.y - mean) * inv * gv.y + bv.y;
    o4.z = (v.z - mean) * inv * gv.z + bv.z;
    o4.w = (v.w - mean) * inv * gv.w + bv.w;
    ((float4*)(out + row * (size_t)Dz))[tid] = o4;
}

// ---------------- elementwise add ----------------
__global__ void add_kernel(const float* __restrict__ a, const float* __restrict__ b,
                           float* __restrict__ c)
{
    int i = blockIdx.x * blockDim.x + threadIdx.x;
    float4 av = ((const float4*)a)[i];
    float4 bv = ((const float4*)b)[i];
    float4 cv;
    cv.x = av.x + bv.x; cv.y = av.y + bv.y; cv.z = av.z + bv.z; cv.w = av.w + bv.w;
    ((float4*)c)[i] = cv;
}

// ---------------- tf32 MMA helpers ------------------------------------------
__device__ __forceinline__ void mma_tf32(float* c, const uint32_t* a, const uint32_t* b) {
    asm volatile("mma.sync.aligned.m16n8k8.row.col.f32.tf32.tf32.f32 "
                 "{%0,%1,%2,%3},{%4,%5,%6,%7},{%8,%9},{%0,%1,%2,%3};"
                 : "+f"(c[0]), "+f"(c[1]), "+f"(c[2]), "+f"(c[3])
                 : "r"(a[0]), "r"(a[1]), "r"(a[2]), "r"(a[3]), "r"(b[0]), "r"(b[1]));
}
__device__ __forceinline__ void cp16(uint32_t dst, const void* src) {
    asm volatile("cp.async.cg.shared.global [%0], [%1], 16;" :: "r"(dst), "l"(src));
}

// ---------------- tf32 tensor-core GEMM -------------------------------------
// C[M,N] = A[M,K] @ B.  TB=false: B row-major [K,N]; TB=true: B row-major [N,K].
template<int BM, int BN, int WM, int WN, bool TB>
__global__ void __launch_bounds__((BM/WM)*(BN/WN)*32)
tgemm(int K,
      const float* __restrict__ A, int lda,
      const float* __restrict__ B, int ldb,
      float* __restrict__ C, int ldc,
      const float* __restrict__ bias,
      const float* __restrict__ res, int ldres, int relu)
{
    constexpr int BK = 16;
    constexpr int NWARP = (BM/WM)*(BN/WN);
    constexpr int THREADS = NWARP*32;
    constexpr int ASTR = BK + 4;
    constexpr int BSTR = TB ? (BK + 4) : (BN + 8);
    constexpr int BROWS = TB ? BN : BK;
    constexpr int MI = WM/16, NJ = WN/8;

    __shared__ __align__(16) float As[2][BM*ASTR];
    __shared__ __align__(16) float Bs[2][BROWS*BSTR];

    int tid = threadIdx.x;
    int bm = blockIdx.y*BM, bn = blockIdx.x*BN;
    int warp = tid >> 5, lane = tid & 31, g = lane >> 2, tg = lane & 3;
    constexpr int WNC = BN/WN;
    int wn = warp % WNC, wm = warp / WNC;

    uint32_t asb = (uint32_t)__cvta_generic_to_shared(&As[0][0]);
    uint32_t bsb = (uint32_t)__cvta_generic_to_shared(&Bs[0][0]);

    const int NT = K / BK;

    auto issue = [&](int kt) {
        int buf = kt & 1;
        #pragma unroll
        for (int e = tid; e < BM*(BK/4); e += THREADS) {
            int r = e >> 2, c = (e & 3) * 4;
            cp16(asb + (uint32_t)(buf*BM*ASTR + r*ASTR + c)*4u,
                 A + (size_t)(bm + r)*lda + kt*BK + c);
        }
        if (TB) {
            #pragma unroll
            for (int e = tid; e < BN*(BK/4); e += THREADS) {
                int r = e >> 2, c = (e & 3) * 4;
                cp16(bsb + (uint32_t)(buf*BROWS*BSTR + r*BSTR + c)*4u,
                     B + (size_t)(bn + r)*ldb + kt*BK + c);
            }
        } else {
            #pragma unroll
            for (int e = tid; e < BK*(BN/4); e += THREADS) {
                int r = e / (BN/4), c = (e % (BN/4)) * 4;
                cp16(bsb + (uint32_t)(buf*BROWS*BSTR + r*BSTR + c)*4u,
                     B + (size_t)(kt*BK + r)*ldb + bn + c);
            }
        }
        asm volatile("cp.async.commit_group;");
    };

    float acc[MI][NJ][4] = {};

    issue(0);
    for (int kt = 0; kt < NT; kt++) {
        if (kt + 1 < NT) { issue(kt + 1); asm volatile("cp.async.wait_group 1;"); }
        else             { asm volatile("cp.async.wait_group 0;"); }
        __syncthreads();

        int buf = kt & 1;
        const float* ap = &As[buf][0];
        const float* bp = &Bs[buf][0];
        #pragma unroll
        for (int ks = 0; ks < 2; ks++) {
            uint32_t a[MI][4], b[NJ][2];
            #pragma unroll
            for (int mi = 0; mi < MI; mi++) {
                int m0 = wm*WM + mi*16 + g;
                a[mi][0] = __float_as_uint(ap[(m0    )*ASTR + ks*8 + tg    ]);
                a[mi][1] = __float_as_uint(ap[(m0 + 8)*ASTR + ks*8 + tg    ]);
                a[mi][2] = __float_as_uint(ap[(m0    )*ASTR + ks*8 + tg + 4]);
                a[mi][3] = __float_as_uint(ap[(m0 + 8)*ASTR + ks*8 + tg + 4]);
            }
            #pragma unroll
            for (int j = 0; j < NJ; j++) {
                int n0 = wn*WN + j*8 + g;
                if (TB) {
                    b[j][0] = __float_as_uint(bp[n0*BSTR + ks*8 + tg    ]);
                    b[j][1] = __float_as_uint(bp[n0*BSTR + ks*8 + tg + 4]);
                } else {
                    b[j][0] = __float_as_uint(bp[(ks*8 + tg    )*BSTR + n0]);
                    b[j][1] = __float_as_uint(bp[(ks*8 + tg + 4)*BSTR + n0]);
                }
            }
            #pragma unroll
            for (int mi = 0; mi < MI; mi++)
                #pragma unroll
                for (int j = 0; j < NJ; j++)
                    mma_tf32(acc[mi][j], a[mi], b[j]);
        }
        __syncthreads();
    }

    #pragma unroll
    for (int mi = 0; mi < MI; mi++) {
        #pragma unroll
        for (int j = 0; j < NJ; j++) {
            int m0 = bm + wm*WM + mi*16 + g;
            int n0 = bn + wn*WN + j*8 + 2*tg;
            float v0 = acc[mi][j][0], v1 = acc[mi][j][1];
            float v2 = acc[mi][j][2], v3 = acc[mi][j][3];
            if (bias) {
                float b0 = bias[n0], b1 = bias[n0 + 1];
                v0 += b0; v1 += b1; v2 += b0; v3 += b1;
            }
            if (res) {
                v0 += res[(size_t)m0*ldres + n0];
                v1 += res[(size_t)m0*ldres + n0 + 1];
                v2 += res[(size_t)(m0 + 8)*ldres + n0];
                v3 += res[(size_t)(m0 + 8)*ldres + n0 + 1];
            }
            if (relu) {
                v0 = fmaxf(v0, 0.f); v1 = fmaxf(v1, 0.f);
                v2 = fmaxf(v2, 0.f); v3 = fmaxf(v3, 0.f);
            }
            *(float2*)&C[(size_t)m0*ldc + n0]       = make_float2(v0, v1);
            *(float2*)&C[(size_t)(m0 + 8)*ldc + n0] = make_float2(v2, v3);
        }
    }
}

// ---------------- fused flash cross-attention --------------------------------
// grid (S1/128, B*H), block 256 (8 warps). Warp w owns Q rows [w*16, w*16+16).
// Per S2-tile of 64: S = Q K^T (tf32 MMA), mask+scale, online softmax,
// O += P V (tf32 MMA, P staged via SMEM). K/V double-buffered via cp.async.
#define KSTR 68
#define VSTR 72
#define PSTR 68
#define FLASH_SMEM ((2*64*KSTR + 2*64*VSTR + 128*PSTR + S2z) * 4)

__global__ void __launch_bounds__(256)
flash_kernel(const float* __restrict__ Q, const float* __restrict__ Kg,
             const float* __restrict__ Vg, const int* __restrict__ mask,
             float* __restrict__ O)
{
    extern __shared__ float sm[];
    float* Ks = sm;
    float* Vs = Ks + 2*64*KSTR;
    float* Ps = Vs + 2*64*VSTR;
    float* Mf = Ps + 128*PSTR;

    int bh = blockIdx.y;
    int b = bh / Hz, h = bh % Hz;
    int q0 = blockIdx.x * 128;
    int tid = threadIdx.x, warp = tid >> 5, lane = tid & 31, g = lane >> 2, tg = lane & 3;

    const float* Qb = Q  + ((size_t)(b*S1z + q0))*Dz + h*DKz;
    const float* Kb = Kg + ((size_t)b*S2z)*Dz + h*DKz;
    const float* Vb = Vg + ((size_t)b*S2z)*Dz + h*DKz;

    // mask -> 0/1 floats (whole row for this batch)
    for (int i = tid; i < S2z; i += 256) Mf[i] = mask[(size_t)b*S2z + i] ? 1.f : 0.f;

    // Q fragments, raw fp32 bits as tf32 (one-time)
    uint32_t qa[8][4];
    {
        int ml = warp*16 + g, mh = ml + 8;
        #pragma unroll
        for (int ki = 0; ki < 8; ki++) {
            qa[ki][0] = __float_as_uint(Qb[(size_t)ml*Dz + ki*8 + tg]);
            qa[ki][1] = __float_as_uint(Qb[(size_t)mh*Dz + ki*8 + tg]);
            qa[ki][2] = __float_as_uint(Qb[(size_t)ml*Dz + ki*8 + tg + 4]);
            qa[ki][3] = __float_as_uint(Qb[(size_t)mh*Dz + ki*8 + tg + 4]);
        }
    }

    uint32_t ksb = (uint32_t)__cvta_generic_to_shared(Ks);
    uint32_t vsb = (uint32_t)__cvta_generic_to_shared(Vs);

    auto issue = [&](int t) {
        int buf = t & 1;
        #pragma unroll
        for (int i = 0; i < 4; i++) {
            int e = tid + i*256;
            int r = e >> 4, c = (e & 15) * 4;
            cp16(ksb + (uint32_t)(buf*64*KSTR + r*KSTR + c)*4u,
                 Kb + (size_t)(t*64 + r)*Dz + c);
            cp16(vsb + (uint32_t)(buf*64*VSTR + r*VSTR + c)*4u,
                 Vb + (size_t)(t*64 + r)*Dz + c);
        }
        asm volatile("cp.async.commit_group;");
    };

    float s_acc[8][4];
    float o_acc[8][4] = {};
    float m_lo = -INFINITY, m_hi = -INFINITY, l_lo = 0.f, l_hi = 0.f;
    int rl = warp*16 + g, rh = rl + 8;

    issue(0);
    for (int t = 0; t < S2z/64; t++) {
        if (t + 1 < S2z/64) { issue(t + 1); asm volatile("cp.async.wait_group 1;"); }
        else                { asm volatile("cp.async.wait_group 0;"); }
        __syncthreads();
        int buf = t & 1;
        const float* kp = Ks + buf*64*KSTR;
        const float* vp = Vs + buf*64*VSTR;

        // ---- S = Q @ K^T ----
        #pragma unroll
        for (int j = 0; j < 8; j++)
            s_acc[j][0] = s_acc[j][1] = s_acc[j][2] = s_acc[j][3] = 0.f;
        #pragma unroll
        for (int ki = 0; ki < 8; ki++) {
            #pragma unroll
            for (int j = 0; j < 8; j++) {
                int n0 = j*8 + g;
                uint32_t bb[2] = {
                    __float_as_uint(kp[n0*KSTR + ki*8 + tg]),
                    __float_as_uint(kp[n0*KSTR + ki*8 + tg + 4]) };
                mma_tf32(s_acc[j], qa[ki], bb);
            }
        }

        // ---- mask + scale, online softmax ----
        float rmax_lo = -INFINITY, rmax_hi = -INFINITY;
        #pragma unroll
        for (int j = 0; j < 8; j++) {
            int c0 = t*64 + j*8 + 2*tg;
            float mf0 = Mf[c0], mf1 = Mf[c0 + 1];
            s_acc[j][0] = (mf0 != 0.f) ? s_acc[j][0]*0.125f : -1e9f;
            s_acc[j][1] = (mf1 != 0.f) ? s_acc[j][1]*0.125f : -1e9f;
            s_acc[j][2] = (mf0 != 0.f) ? s_acc[j][2]*0.125f : -1e9f;
            s_acc[j][3] = (mf1 != 0.f) ? s_acc[j][3]*0.125f : -1e9f;
            rmax_lo = fmaxf(rmax_lo, fmaxf(s_acc[j][0], s_acc[j][1]));
            rmax_hi = fmaxf(rmax_hi, fmaxf(s_acc[j][2], s_acc[j][3]));
        }
        rmax_lo = fmaxf(rmax_lo, __shfl_xor_sync(0xffffffffu, rmax_lo, 1));
        rmax_lo = fmaxf(rmax_lo, __shfl_xor_sync(0xffffffffu, rmax_lo, 2));
        rmax_hi = fmaxf(rmax_hi, __shfl_xor_sync(0xffffffffu, rmax_hi, 1));
        rmax_hi = fmaxf(rmax_hi, __shfl_xor_sync(0xffffffffu, rmax_hi, 2));
        float mn_lo = fmaxf(m_lo, rmax_lo), mn_hi = fmaxf(m_hi, rmax_hi);
        float al_lo = __expf(m_lo - mn_lo), al_hi = __expf(m_hi - mn_hi);
        m_lo = mn_lo; m_hi = mn_hi;

        float sum_lo = 0.f, sum_hi = 0.f;
        #pragma unroll
        for (int j = 0; j < 8; j++) {
            float p0 = __expf(s_acc[j][0] - mn_lo);
            float p1 = __expf(s_acc[j][1] - mn_lo);
            float p2 = __expf(s_acc[j][2] - mn_hi);
            float p3 = __expf(s_acc[j][3] - mn_hi);
            sum_lo += p0 + p1; sum_hi += p2 + p3;
            int c = j*8 + 2*tg;
            *(float2*)&Ps[rl*PSTR + c] = make_float2(p0, p1);
            *(float2*)&Ps[rh*PSTR + c] = make_float2(p2, p3);
        }
        sum_lo += __shfl_xor_sync(0xffffffffu, sum_lo, 1);
        sum_lo += __shfl_xor_sync(0xffffffffu, sum_lo, 2);
        sum_hi += __shfl_xor_sync(0xffffffffu, sum_hi, 1);
        sum_hi += __shfl_xor_sync(0xffffffffu, sum_hi, 2);
        l_lo = al_lo*l_lo + sum_lo;
        l_hi = al_hi*l_hi + sum_hi;
        #pragma unroll
        for (int j = 0; j < 8; j++) {
            o_acc[j][0] *= al_lo; o_acc[j][1] *= al_lo;
            o_acc[j][2] *= al_hi; o_acc[j][3] *= al_hi;
        }
        __syncwarp();   // Ps region is per-warp; order STS before LDS across lanes

        // ---- O += P @ V ----
        #pragma unroll
        for (int ki = 0; ki < 8; ki++) {
            int k0 = ki*8 + tg;
            uint32_t pa[4];
            pa[0] = __float_as_uint(Ps[rl*PSTR + k0]);
            pa[1] = __float_as_uint(Ps[rh*PSTR + k0]);
            pa[2] = __float_as_uint(Ps[rl*PSTR + k0 + 4]);
            pa[3] = __float_as_uint(Ps[rh*PSTR + k0 + 4]);
            #pragma unroll
            for (int j = 0; j < 8; j++) {
                int n0 = j*8 + g;
                uint32_t bb[2] = {
                    __float_as_uint(vp[(ki*8 + tg    )*VSTR + n0]),
                    __float_as_uint(vp[(ki*8 + tg + 4)*VSTR + n0]) };
                mma_tf32(o_acc[j], pa, bb);
            }
        }
        __syncthreads();   // all warps done with this K/V buffer before re-fill
    }

    // ---- epilogue: divide by l, store ----
    float il_lo = 1.f / l_lo, il_hi = 1.f / l_hi;
    float* Ob = O + ((size_t)(b*S1z + q0))*Dz + h*DKz;
    #pragma unroll
    for (int j = 0; j < 8; j++) {
        int c = j*8 + 2*tg;
        *(float2*)&Ob[(size_t)rl*Dz + c] =
            make_float2(o_acc[j][0]*il_lo, o_acc[j][1]*il_lo);
        *(float2*)&Ob[(size_t)rh*Dz + c] =
            make_float2(o_acc[j][2]*il_hi, o_acc[j][3]*il_hi);
    }
}

// ---------------- host orchestration ----------------
extern "C" void kernel_launch(void* const* d_in, const int* in_sizes, int n_in,
                              void* d_out, int out_size)
{
    const float* x     = (const float*)d_in[0];
    const float* kv    = (const float*)d_in[1];
    const int*   mask  = (const int*)  d_in[2];
    const float* ln1_g = (const float*)d_in[3];
    const float* ln1_b = (const float*)d_in[4];
    const float* qw[2] = { (const float*)d_in[5],  (const float*)d_in[10] };
    const float* kw[2] = { (const float*)d_in[6],  (const float*)d_in[11] };
    const float* vw[2] = { (const float*)d_in[7],  (const float*)d_in[12] };
    const float* ow[2] = { (const float*)d_in[8],  (const float*)d_in[13] };
    const float* ob[2] = { (const float*)d_in[9],  (const float*)d_in[14] };
    const float* ln2_g = (const float*)d_in[15];
    const float* ln2_b = (const float*)d_in[16];
    const float* w1    = (const float*)d_in[17];
    const float* b1    = (const float*)d_in[18];
    const float* w2    = (const float*)d_in[19];
    const float* b2    = (const float*)d_in[20];
    float* out = (float*)d_out;

    float *y, *kvn, *q, *k, *v, *o, *x2, *hbuf;
    cudaGetSymbolAddress((void**)&y,    g_y);
    cudaGetSymbolAddress((void**)&kvn,  g_kvn);
    cudaGetSymbolAddress((void**)&q,    g_q);
    cudaGetSymbolAddress((void**)&k,    g_k);
    cudaGetSymbolAddress((void**)&v,    g_v);
    cudaGetSymbolAddress((void**)&o,    g_o);
    cudaGetSymbolAddress((void**)&x2,   g_x2);
    cudaGetSymbolAddress((void**)&hbuf, g_h);

    cudaFuncSetAttribute(flash_kernel,
        cudaFuncAttributeMaxDynamicSharedMemorySize, FLASH_SMEM);

    const int M = Bz * S1z;   // 4096

    ln_kernel<<<Bz * S1z, 256>>>(x,  y,   ln1_g, ln1_b);
    ln_kernel<<<Bz * S2z, 256>>>(kv, kvn, ln1_g, ln1_b);

    dim3 gProj(Dz/128, M/128);            // (8, 32)
    dim3 gFlash(S1z/128, Bz*Hz);          // (8, 64)

    for (int l = 0; l < 2; l++) {
        tgemm<128,128,32,64,false><<<gProj, 256>>>(Dz, y,   Dz, qw[l], Dz, q, Dz,
            nullptr, nullptr, 0, 0);
        tgemm<128,128,32,64,false><<<gProj, 256>>>(Dz, kvn, Dz, kw[l], Dz, k, Dz,
            nullptr, nullptr, 0, 0);
        tgemm<128,128,32,64,false><<<gProj, 256>>>(Dz, kvn, Dz, vw[l], Dz, v, Dz,
            nullptr, nullptr, 0, 0);

        flash_kernel<<<gFlash, 256, FLASH_SMEM>>>(q, k, v, mask, o);

        // y = O @ ow + ob + y   (residual fused)
        tgemm<128,128,32,64,false><<<gProj, 256>>>(Dz, o, Dz, ow[l], Dz, y, Dz,
            ob[l], y, Dz, 0);
    }

    // x2 = x + y
    add_kernel<<<(M * Dz) / (256 * 4), 256>>>(x, y, x2);

    // y = LN(x2)
    ln_kernel<<<M, 256>>>(x2, y, ln2_g, ln2_b);

    // h = relu(y @ w1 + b1)
    dim3 gF1(FFNz/128, M/128);
    tgemm<128,128,32,64,false><<<gF1, 256>>>(Dz, y, Dz, w1, FFNz, hbuf, FFNz,
        b1, nullptr, 0, 1);

    // out = h @ w2 + b2 + x2
    tgemm<128,128,32,64,false><<<gProj, 256>>>(FFNz, hbuf, FFNz, w2, Dz, out, Dz,
        b2, x2, Dz, 0);
}